// round 4
// baseline (speedup 1.0000x reference)
#include <cuda_runtime.h>

// Inputs: q, r, Ek, Ev, Mk, Mv0, We, be, Wa, ba, Wf, bf, Wp, bp
// q,r int32 [64,512]; rest float32. Output: p [64,512] float32.

#define NUM_C 1000
#define DIM   128
#define MSZ   64
#define BB    64
#define LL    512
#define NTOK  (BB*LL)

typedef unsigned long long ull;

// ---------------- device scratch ----------------
__device__ float g_w  [NUM_C*MSZ];     // softmax(Ek[q] @ Mk^T)          [1000,64]
__device__ float g_ne [2*NUM_C*DIM];   // -sigmoid(Ev@We+be)  (negated!) [2000,128]
__device__ float g_a  [2*NUM_C*DIM];   // tanh(Ev@Wa+ba)                 [2000,128]
__device__ float g_fk [NUM_C*DIM];     // Ek@Wf[128:256] + bf            [1000,128]
__device__ float g_read[NTOK*DIM];     // scan output                    [B*L,128]

// ---------------- f32x2 helpers ----------------
__device__ __forceinline__ ull fma2(ull a, ull b, ull c) {
    ull d; asm("fma.rn.f32x2 %0, %1, %2, %3;" : "=l"(d) : "l"(a), "l"(b), "l"(c)); return d;
}
__device__ __forceinline__ ull add2(ull a, ull b) {
    ull d; asm("add.rn.f32x2 %0, %1, %2;" : "=l"(d) : "l"(a), "l"(b)); return d;
}
__device__ __forceinline__ ull pack2(float x, float y) {
    ull d; asm("mov.b64 %0, {%1, %2};" : "=l"(d) : "f"(x), "f"(y)); return d;
}
__device__ __forceinline__ float2 unpack2(ull v) {
    float2 r; asm("mov.b64 {%0, %1}, %2;" : "=f"(r.x), "=f"(r.y) : "l"(v)); return r;
}
__device__ __forceinline__ float sigmoid_fast(float x) {
    return __fdividef(1.0f, 1.0f + __expf(-x));
}
__device__ __forceinline__ float tanh_fast(float x) {
    return 1.0f - __fdividef(2.0f, __expf(2.0f * x) + 1.0f);
}

// ======================================================================
// Kernel 1a: softmax correlation-weight table. 50 blocks x 10 q-pairs.
// ======================================================================
#define WT_BLOCKS 50
#define WT_PAIRS  10

__global__ void __launch_bounds__(128) k_wtab(const float* __restrict__ Ek,
                                              const float* __restrict__ Mk) {
    __shared__ float mk[MSZ][DIM + 2];
    __shared__ float ek[2][2][DIM];
    __shared__ float xmax[2][4];
    __shared__ float xsum[2][4];

    int bid = blockIdx.x, t = threadIdx.x;
    int h = t >> 6, m = t & 63;
    int lane = t & 31, wid = t >> 5;

    for (int idx = t; idx < MSZ * DIM; idx += 128)
        mk[idx >> 7][idx & 127] = Mk[idx];
    __syncthreads();

    ull mk2[64];
#pragma unroll
    for (int j = 0; j < 64; j++)
        mk2[j] = pack2(mk[m][2*j], mk[m][2*j + 1]);

    int qp0 = bid * WT_PAIRS;
    float e0 = Ek[(2*qp0)*DIM + t];
    float e1 = Ek[(2*qp0 + 1)*DIM + t];
    int pb = 0;
    for (int i = 0; i < WT_PAIRS; i++) {
        ek[pb][0][t] = e0;
        ek[pb][1][t] = e1;
        __syncthreads();
        if (i + 1 < WT_PAIRS) {
            e0 = Ek[(2*(qp0 + i + 1))*DIM + t];
            e1 = Ek[(2*(qp0 + i + 1) + 1)*DIM + t];
        }
        const ull* ep = (const ull*)ek[pb][h];
        ull a0 = 0ULL, a1 = 0ULL;
#pragma unroll
        for (int j = 0; j < 64; j += 2) {
            a0 = fma2(ep[j],   mk2[j],   a0);
            a1 = fma2(ep[j+1], mk2[j+1], a1);
        }
        float2 ac = unpack2(add2(a0, a1));
        float lv = ac.x + ac.y;

        float wm = lv;
#pragma unroll
        for (int o = 16; o > 0; o >>= 1)
            wm = fmaxf(wm, __shfl_xor_sync(0xffffffffu, wm, o));
        if (lane == 0) xmax[pb][wid] = wm;
        __syncthreads();
        float mx = fmaxf(xmax[pb][h*2], xmax[pb][h*2 + 1]);
        float ev = __expf(lv - mx);
        float ws = ev;
#pragma unroll
        for (int o = 16; o > 0; o >>= 1)
            ws += __shfl_xor_sync(0xffffffffu, ws, o);
        if (lane == 0) xsum[pb][wid] = ws;
        __syncthreads();
        float s = xsum[pb][h*2] + xsum[pb][h*2 + 1];
        g_w[(2*(qp0 + i) + h)*MSZ + m] = __fdividef(ev, s);
        pb ^= 1;
    }
}

// ======================================================================
// Kernel 1b: column-GEMM tables, 250 blocks x 20 rows (2 rows/iter).
// ======================================================================
__global__ void __launch_bounds__(128) k_cgemm(
        const float* __restrict__ Ek, const float* __restrict__ Ev,
        const float* __restrict__ We, const float* __restrict__ be,
        const float* __restrict__ Wa, const float* __restrict__ ba,
        const float* __restrict__ Wf, const float* __restrict__ bf) {
    __shared__ __align__(16) float sv[2][DIM];
    int cb = blockIdx.x, t = threadIdx.x;
    const float *W, *bias, *rows;
    float* outp;
    int mode, row0;
    if (cb < 100)      { W = We;           bias = be; rows = Ev; outp = g_ne; mode = 0; row0 = cb*20; }
    else if (cb < 200) { W = Wa;           bias = ba; rows = Ev; outp = g_a;  mode = 1; row0 = (cb-100)*20; }
    else               { W = Wf + DIM*DIM; bias = bf; rows = Ek; outp = g_fk; mode = 2; row0 = (cb-200)*20; }

    ull w2[64];
#pragma unroll
    for (int j = 0; j < 64; j++)
        w2[j] = pack2(W[(2*j)*DIM + t], W[(2*j+1)*DIM + t]);
    float bv = bias[t];

    float nA = rows[row0*DIM + t];
    float nB = rows[(row0 + 1)*DIM + t];
    for (int i = 0; i < 10; i++) {
        sv[0][t] = nA;
        sv[1][t] = nB;
        __syncthreads();
        if (i < 9) {
            nA = rows[(row0 + 2*i + 2)*DIM + t];
            nB = rows[(row0 + 2*i + 3)*DIM + t];
        }
        const ull* sa = (const ull*)sv[0];
        const ull* sb = (const ull*)sv[1];
        ull aA0 = pack2(bv, 0.f), aA1 = 0ULL;
        ull aB0 = pack2(bv, 0.f), aB1 = 0ULL;
#pragma unroll
        for (int j = 0; j < 64; j += 2) {
            aA0 = fma2(sa[j],   w2[j],   aA0);
            aA1 = fma2(sa[j+1], w2[j+1], aA1);
            aB0 = fma2(sb[j],   w2[j],   aB0);
            aB1 = fma2(sb[j+1], w2[j+1], aB1);
        }
        float2 fA = unpack2(add2(aA0, aA1));
        float2 fB = unpack2(add2(aB0, aB1));
        float gA = fA.x + fA.y, gB = fB.x + fB.y;
        float oA, oB;
        if (mode == 0)      { oA = -sigmoid_fast(gA); oB = -sigmoid_fast(gB); }
        else if (mode == 1) { oA = tanh_fast(gA);     oB = tanh_fast(gB); }
        else                { oA = gA;                oB = gB; }
        outp[(row0 + 2*i)*DIM + t]     = oA;
        outp[(row0 + 2*i + 1)*DIM + t] = oB;
        __syncthreads();
    }
}

// ======================================================================
// Kernel 2: barrier-free sequential scan.
// grid 128 = (batch, half); block 128 = 4 independent warps.
// Warp covers 16 cols x 64 m; lane = (m-quarter)*8 + col-pair.
// Read-reduction = intra-warp shfl_xor (off critical path). No bars in loop.
// ======================================================================
struct SD { float w[16]; ull ne2, a2; };

__device__ __forceinline__ void sd_load(SD& s, const int2* __restrict__ sidx,
                                        int l, int mq, int eoff) {
    int lc = (l < LL) ? l : (LL - 1);
    int2 ix = sidx[lc];
    const float4* wp = (const float4*)(g_w + ix.x + mq*16);
    float4 w0 = wp[0], w1 = wp[1], w2 = wp[2], w3 = wp[3];
    s.w[0]=w0.x; s.w[1]=w0.y; s.w[2]=w0.z; s.w[3]=w0.w;
    s.w[4]=w1.x; s.w[5]=w1.y; s.w[6]=w1.z; s.w[7]=w1.w;
    s.w[8]=w2.x; s.w[9]=w2.y; s.w[10]=w2.z; s.w[11]=w2.w;
    s.w[12]=w3.x; s.w[13]=w3.y; s.w[14]=w3.z; s.w[15]=w3.w;
    s.ne2 = *(const ull*)(g_ne + ix.y + eoff);
    s.a2  = *(const ull*)(g_a  + ix.y + eoff);
}

__device__ __forceinline__ void scan_step(const SD& s, ull mv[16], int l,
                                          int mq, float* rbase) {
    ull r0 = 0ULL, r1 = 0ULL;
#pragma unroll
    for (int j = 0; j < 16; j++) {
        ull w2 = pack2(s.w[j], s.w[j]);
        ull tt = fma2(mv[j], s.ne2, s.a2);        // t = a - mv*e   (ne = -e)
        if (j & 1) r1 = fma2(w2, mv[j], r1);      // read += w * mv_old
        else       r0 = fma2(w2, mv[j], r0);
        mv[j] = fma2(w2, tt, mv[j]);              // mv += w * t
    }
    ull racc = add2(r0, r1);
    racc = add2(racc, __shfl_xor_sync(0xffffffffu, racc, 8));
    racc = add2(racc, __shfl_xor_sync(0xffffffffu, racc, 16));
    if (mq == 0) *(ull*)(rbase + l*DIM) = racc;
}

__global__ void __launch_bounds__(128, 1) k_scan(const float* __restrict__ Mv0,
                                                 const int* __restrict__ q,
                                                 const int* __restrict__ r) {
    __shared__ int2 sidx[LL];
    int bx = blockIdx.x, b = bx >> 1, h = bx & 1;
    int tid = threadIdx.x, wid = tid >> 5, lane = tid & 31;
    int mq = lane >> 3, cpi = lane & 7;

    for (int i = tid; i < LL; i += 128) {
        int qv = q[b*LL + i], rv = r[b*LL + i];
        sidx[i] = make_int2(qv*MSZ, (qv + NUM_C*rv)*DIM);
    }

    int eoff = h*64 + wid*16 + cpi*2;
    ull mv[16];
#pragma unroll
    for (int j = 0; j < 16; j++)
        mv[j] = *(const ull*)(Mv0 + (mq*16 + j)*DIM + eoff);
    __syncthreads();   // sidx ready; only bar in the kernel

    float* rb = g_read + (b*LL)*DIM + eoff;

    SD A0, A1, B0, B1;
    sd_load(A0, sidx, 0, mq, eoff);
    sd_load(A1, sidx, 1, mq, eoff);
    sd_load(B0, sidx, 2, mq, eoff);
    sd_load(B1, sidx, 3, mq, eoff);

    for (int l = 0; l < LL; l += 4) {
        scan_step(A0, mv, l+0, mq, rb);
        scan_step(A1, mv, l+1, mq, rb);
        sd_load(A0, sidx, l+4, mq, eoff);
        sd_load(A1, sidx, l+5, mq, eoff);
        scan_step(B0, mv, l+2, mq, rb);
        scan_step(B1, mv, l+3, mq, rb);
        sd_load(B0, sidx, l+6, mq, eoff);
        sd_load(B1, sidx, l+7, mq, eoff);
    }
}

// ======================================================================
// Kernel 3: f = tanh(read@Wf_r + fk), p = sigmoid(f.Wp + bp).
// 4 tokens/iter, double-buffered shared, next-iter loads prefetched.
// ======================================================================
__global__ void __launch_bounds__(128, 2) k_fp(const int* __restrict__ q,
                                               const float* __restrict__ Wf,
                                               const float* __restrict__ Wp,
                                               const float* __restrict__ bp,
                                               float* __restrict__ out) {
    __shared__ __align__(16) ull rr[2][4][DIM];
    __shared__ ull part[2][4][64];
    __shared__ float red[2][4][2];
    int tid = threadIdx.x;
    int g = tid >> 6, p = tid & 63;

    ull wf[64];
#pragma unroll
    for (int j = 0; j < 64; j++)
        wf[j] = *(const ull*)(Wf + (g*64 + j)*DIM + 2*p);
    float wpx = Wp[2*p], wpy = Wp[2*p + 1];
    float bpv = bp[0];

    const int stride = gridDim.x * 4;
    int tok0 = blockIdx.x * 4;

    float rv[4];
    ull fk0[4] = {0ULL, 0ULL, 0ULL, 0ULL};
    if (tok0 < NTOK) {
#pragma unroll
        for (int tt = 0; tt < 4; tt++)
            rv[tt] = g_read[(tok0 + tt)*DIM + tid];
        if (g == 0) {
#pragma unroll
            for (int tt = 0; tt < 4; tt++)
                fk0[tt] = *(const ull*)(g_fk + q[tok0 + tt]*DIM + 2*p);
        }
    }

    int pb = 0;
    for (; tok0 < NTOK; tok0 += stride) {
#pragma unroll
        for (int tt = 0; tt < 4; tt++)
            rr[pb][tt][tid] = pack2(rv[tt], rv[tt]);
        __syncthreads();                               // A

        // prefetch next iteration (lands under the FMA burst below)
        int tokn = tok0 + stride;
        float rvn[4] = {0.f, 0.f, 0.f, 0.f};
        ull fkn[4] = {0ULL, 0ULL, 0ULL, 0ULL};
        if (tokn < NTOK) {
#pragma unroll
            for (int tt = 0; tt < 4; tt++)
                rvn[tt] = g_read[(tokn + tt)*DIM + tid];
            if (g == 0) {
#pragma unroll
                for (int tt = 0; tt < 4; tt++)
                    fkn[tt] = *(const ull*)(g_fk + q[tokn + tt]*DIM + 2*p);
            }
        }

        ull acc0[4], acc1[4];
#pragma unroll
        for (int tt = 0; tt < 4; tt++) { acc0[tt] = fk0[tt]; acc1[tt] = 0ULL; }
#pragma unroll
        for (int j = 0; j < 32; j++) {
#pragma unroll
            for (int tt = 0; tt < 4; tt++) {
                ulonglong2 v = ((const ulonglong2*)&rr[pb][tt][g*64])[j];
                acc0[tt] = fma2(wf[2*j],     v.x, acc0[tt]);
                acc1[tt] = fma2(wf[2*j + 1], v.y, acc1[tt]);
            }
        }
        ull a4[4];
#pragma unroll
        for (int tt = 0; tt < 4; tt++) a4[tt] = add2(acc0[tt], acc1[tt]);

        if (g == 1) {
#pragma unroll
            for (int tt = 0; tt < 4; tt++) part[pb][tt][p] = a4[tt];
        }
        __syncthreads();                               // B
        if (g == 0) {
            float pv[4];
#pragma unroll
            for (int tt = 0; tt < 4; tt++) {
                float2 f = unpack2(add2(a4[tt], part[pb][tt][p]));
                pv[tt] = fmaf(tanh_fast(f.x), wpx, tanh_fast(f.y) * wpy);
            }
#pragma unroll
            for (int o = 16; o > 0; o >>= 1) {
#pragma unroll
                for (int tt = 0; tt < 4; tt++)
                    pv[tt] += __shfl_xor_sync(0xffffffffu, pv[tt], o);
            }
            if ((tid & 31) == 0) {
#pragma unroll
                for (int tt = 0; tt < 4; tt++) red[pb][tt][tid >> 5] = pv[tt];
            }
        }
        __syncthreads();                               // C
        if (tid < 4)
            out[tok0 + tid] = sigmoid_fast(red[pb][tid][0] + red[pb][tid][1] + bpv);

        pb ^= 1;
#pragma unroll
        for (int tt = 0; tt < 4; tt++) { rv[tt] = rvn[tt]; fk0[tt] = fkn[tt]; }
    }
}

// ---------------- launch ----------------
extern "C" void kernel_launch(void* const* d_in, const int* in_sizes, int n_in,
                              void* d_out, int out_size) {
    const int*   q   = (const int*)d_in[0];
    const int*   r   = (const int*)d_in[1];
    const float* Ek  = (const float*)d_in[2];
    const float* Ev  = (const float*)d_in[3];
    const float* Mk  = (const float*)d_in[4];
    const float* Mv0 = (const float*)d_in[5];
    const float* We  = (const float*)d_in[6];
    const float* be  = (const float*)d_in[7];
    const float* Wa  = (const float*)d_in[8];
    const float* ba  = (const float*)d_in[9];
    const float* Wf  = (const float*)d_in[10];
    const float* bf  = (const float*)d_in[11];
    const float* Wp  = (const float*)d_in[12];
    const float* bp  = (const float*)d_in[13];
    float* out = (float*)d_out;

    k_wtab<<<WT_BLOCKS, 128>>>(Ek, Mk);
    k_cgemm<<<250, 128>>>(Ek, Ev, We, be, Wa, ba, Wf, bf);
    k_scan<<<2*BB, 128>>>(Mv0, q, r);
    k_fp<<<296, 128>>>(q, Wf, Wp, bp, out);
}